// round 1
// baseline (speedup 1.0000x reference)
#include <cuda_runtime.h>

#define B_   4
#define S_   1024
#define D_   2048
#define H_   32
#define KVH_ 8
#define HD_  64

// Scratch (allocation-free rule: device globals)
__device__ float g_q[B_ * S_ * H_ * HD_];      // [B*S, 2048]
__device__ float g_k[B_ * S_ * KVH_ * HD_];    // [B*S, 512]
__device__ float g_v[B_ * S_ * KVH_ * HD_];    // [B*S, 512]
__device__ float g_attn[B_ * S_ * H_ * HD_];   // [B*S, 2048]  (B,S,H*HD)

// ---------------------------------------------------------------------------
// SGEMM body: C[128x128 tile] = X[M,2048] @ W[2048,ldw], 8x8 split micro-tile
// ---------------------------------------------------------------------------
__device__ __forceinline__ void sgemm_body(
    const float* __restrict__ X,   // row stride 2048
    const float* __restrict__ W,   // row stride ldw
    float* __restrict__ C,         // row stride ldc
    int ldw, int ldc, int wc0, int row0)
{
    __shared__ __align__(16) float As[8][132];
    __shared__ __align__(16) float Bs[8][132];

    const int tid  = threadIdx.x;      // 256 threads
    const int tx   = tid & 15;
    const int ty   = tid >> 4;
    const int ar   = tid >> 1;         // A-load row (0..127)
    const int aseg = tid & 1;          // A-load k-segment
    const int bk   = tid >> 5;         // B-load k row (0..7)
    const int bc   = (tid & 31) << 2;  // B-load col*4

    float acc[8][8];
    #pragma unroll
    for (int i = 0; i < 8; i++)
        #pragma unroll
        for (int j = 0; j < 8; j++) acc[i][j] = 0.f;

    for (int k0 = 0; k0 < 2048; k0 += 8) {
        float4 av = *(const float4*)(X + (size_t)(row0 + ar) * 2048 + k0 + aseg * 4);
        float4 bv = *(const float4*)(W + (size_t)(k0 + bk) * ldw + wc0 + bc);
        __syncthreads();   // previous compute done before overwrite
        As[aseg * 4 + 0][ar] = av.x;
        As[aseg * 4 + 1][ar] = av.y;
        As[aseg * 4 + 2][ar] = av.z;
        As[aseg * 4 + 3][ar] = av.w;
        *(float4*)&Bs[bk][bc] = bv;
        __syncthreads();
        #pragma unroll
        for (int kk = 0; kk < 8; kk++) {
            float a[8], b[8];
            *(float4*)&a[0] = *(const float4*)&As[kk][ty * 4];
            *(float4*)&a[4] = *(const float4*)&As[kk][64 + ty * 4];
            *(float4*)&b[0] = *(const float4*)&Bs[kk][tx * 4];
            *(float4*)&b[4] = *(const float4*)&Bs[kk][64 + tx * 4];
            #pragma unroll
            for (int i = 0; i < 8; i++)
                #pragma unroll
                for (int j = 0; j < 8; j++)
                    acc[i][j] = fmaf(a[i], b[j], acc[i][j]);
        }
    }

    #pragma unroll
    for (int ih = 0; ih < 2; ih++)
        #pragma unroll
        for (int i = 0; i < 4; i++) {
            int r = row0 + ih * 64 + ty * 4 + i;
            #pragma unroll
            for (int jh = 0; jh < 2; jh++) {
                float4 o;
                o.x = acc[ih * 4 + i][jh * 4 + 0];
                o.y = acc[ih * 4 + i][jh * 4 + 1];
                o.z = acc[ih * 4 + i][jh * 4 + 2];
                o.w = acc[ih * 4 + i][jh * 4 + 3];
                *(float4*)(C + (size_t)r * ldc + wc0 + jh * 64 + tx * 4) = o;
            }
        }
}

// Fused QKV projection: N = 2048 (Wq) | 512 (Wk) | 512 (Wv)
__global__ __launch_bounds__(256) void qkv_gemm_kernel(
    const float* __restrict__ X, const float* __restrict__ Wq,
    const float* __restrict__ Wk, const float* __restrict__ Wv)
{
    int col0 = blockIdx.x * 128;
    int row0 = blockIdx.y * 128;
    const float* W; float* C; int ldw, ldc, wc0;
    if (col0 < 2048)      { W = Wq; C = g_q; ldw = 2048; ldc = 2048; wc0 = col0; }
    else if (col0 < 2560) { W = Wk; C = g_k; ldw = 512;  ldc = 512;  wc0 = col0 - 2048; }
    else                  { W = Wv; C = g_v; ldw = 512;  ldc = 512;  wc0 = col0 - 2560; }
    sgemm_body(X, W, C, ldw, ldc, wc0, row0);
}

// Output projection: d_out = g_attn @ Wo
__global__ __launch_bounds__(256) void out_gemm_kernel(
    const float* __restrict__ Wo, float* __restrict__ out)
{
    int col0 = blockIdx.x * 128;
    int row0 = blockIdx.y * 128;
    sgemm_body(g_attn, Wo, out, 2048, 2048, col0, row0);
}

// ---------------------------------------------------------------------------
// RoPE: one thread per (b,s,h,d<32) pair; in-place on g_q (which=0) or g_k (=1)
// ---------------------------------------------------------------------------
__global__ void rope_kernel(const float* __restrict__ cosb,
                            const float* __restrict__ sinb, int which)
{
    float* buf = which ? g_k : g_q;
    int nh = which ? KVH_ : H_;
    int idx = blockIdx.x * blockDim.x + threadIdx.x;
    int total = B_ * S_ * nh * 32;
    if (idx >= total) return;
    int d = idx & 31;
    int h = (idx >> 5) % nh;
    int s = (idx / (32 * nh)) % S_;
    int b = idx / (32 * nh * S_);
    float* row = buf + (((size_t)(b * S_ + s)) * nh + h) * 64;
    float c1 = cosb[s * 64 + d],      s1 = sinb[s * 64 + d];
    float c2 = cosb[s * 64 + d + 32], s2 = sinb[s * 64 + d + 32];
    float x1 = row[d], x2 = row[d + 32];
    row[d]      = x1 * c1 - x2 * s1;   // q*cos + (-q2)*sin
    row[d + 32] = x2 * c2 + x1 * s2;   // q2*cos + q1*sin
}

// ---------------------------------------------------------------------------
// Flash attention fp32: block = (qb 64 rows, head h, batch b), 64-key tiles
// ---------------------------------------------------------------------------
__global__ __launch_bounds__(256) void flash_kernel()
{
    extern __shared__ __align__(16) float sm[];
    float* sQt = sm;                 // [64 d][68] holds Q^T (pre-scaled)
    float* sKP = sm + 64 * 68;       // K as [d][key], reused as P [key][r]
    float* sV  = sm + 2 * 64 * 68;   // [key][68] natural V

    __shared__ float red[64][17];
    __shared__ float row_m[64], row_l[64], row_al[64];

    const int tid = threadIdx.x;     // 256
    const int tx = tid & 15, ty = tid >> 4;
    const int qb = blockIdx.x, h = blockIdx.y, b = blockIdx.z;
    const int kvh = h >> 2;          // N_REP = 4

    const float* qbase = g_q + ((size_t)(b * S_ + qb * 64) * H_ + h) * 64;

    for (int t = tid; t < 1024; t += 256) {     // 64 rows x 16 float4
        int r = t >> 4, d4 = t & 15;
        float4 v4 = *(const float4*)(qbase + (size_t)r * 2048 + d4 * 4);
        sQt[(d4 * 4 + 0) * 68 + r] = v4.x * 0.125f;
        sQt[(d4 * 4 + 1) * 68 + r] = v4.y * 0.125f;
        sQt[(d4 * 4 + 2) * 68 + r] = v4.z * 0.125f;
        sQt[(d4 * 4 + 3) * 68 + r] = v4.w * 0.125f;
    }
    if (tid < 64) { row_m[tid] = -3.0e38f; row_l[tid] = 0.f; }

    float acc[4][4];
    #pragma unroll
    for (int i = 0; i < 4; i++)
        #pragma unroll
        for (int j = 0; j < 4; j++) acc[i][j] = 0.f;

    for (int j0 = 0; j0 < S_; j0 += 64) {
        __syncthreads();   // covers Q/init on first iter, P/V reads otherwise
        const float* kbase = g_k + ((size_t)(b * S_ + j0) * KVH_ + kvh) * 64;
        const float* vbase = g_v + ((size_t)(b * S_ + j0) * KVH_ + kvh) * 64;
        for (int t = tid; t < 1024; t += 256) {
            int r = t >> 4, d4 = t & 15;
            float4 kv = *(const float4*)(kbase + (size_t)r * 512 + d4 * 4);
            sKP[(d4 * 4 + 0) * 68 + r] = kv.x;
            sKP[(d4 * 4 + 1) * 68 + r] = kv.y;
            sKP[(d4 * 4 + 2) * 68 + r] = kv.z;
            sKP[(d4 * 4 + 3) * 68 + r] = kv.w;
            float4 vv = *(const float4*)(vbase + (size_t)r * 512 + d4 * 4);
            *(float4*)&sV[r * 68 + d4 * 4] = vv;
        }
        __syncthreads();

        // S tile: s[i][j] = sum_d Q[r][d] * K[c][d], r=ty*4+i, c=tx*4+j
        float s[4][4];
        #pragma unroll
        for (int i = 0; i < 4; i++)
            #pragma unroll
            for (int j = 0; j < 4; j++) s[i][j] = 0.f;
        #pragma unroll
        for (int d = 0; d < 64; d++) {
            float4 a4 = *(const float4*)&sQt[d * 68 + ty * 4];
            float4 b4 = *(const float4*)&sKP[d * 68 + tx * 4];
            float a[4] = {a4.x, a4.y, a4.z, a4.w};
            float bb[4] = {b4.x, b4.y, b4.z, b4.w};
            #pragma unroll
            for (int i = 0; i < 4; i++)
                #pragma unroll
                for (int j = 0; j < 4; j++)
                    s[i][j] = fmaf(a[i], bb[j], s[i][j]);
        }

        // per-row tile max
        #pragma unroll
        for (int i = 0; i < 4; i++) {
            float m = fmaxf(fmaxf(s[i][0], s[i][1]), fmaxf(s[i][2], s[i][3]));
            red[ty * 4 + i][tx] = m;
        }
        __syncthreads();
        if (tid < 64) {
            float tm = red[tid][0];
            #pragma unroll
            for (int k = 1; k < 16; k++) tm = fmaxf(tm, red[tid][k]);
            float mo = row_m[tid];
            float mn = fmaxf(mo, tm);
            row_al[tid] = __expf(mo - mn);
            row_m[tid]  = mn;
        }
        __syncthreads();

        // p = exp(s - m), rescale acc, stash P^T into sKP (K no longer needed)
        #pragma unroll
        for (int i = 0; i < 4; i++) {
            int r = ty * 4 + i;
            float mn = row_m[r], al = row_al[r];
            float sum = 0.f;
            #pragma unroll
            for (int j = 0; j < 4; j++) {
                float p = __expf(s[i][j] - mn);
                sum += p;
                acc[i][j] *= al;
                sKP[(tx * 4 + j) * 68 + r] = p;
            }
            red[r][tx] = sum;
        }
        __syncthreads();
        if (tid < 64) {
            float sum = 0.f;
            #pragma unroll
            for (int k = 0; k < 16; k++) sum += red[tid][k];
            row_l[tid] = row_l[tid] * row_al[tid] + sum;
        }

        // acc += P @ V : acc[i][j] += sum_kk P[kk][r] * V[kk][c]
        #pragma unroll
        for (int kk = 0; kk < 64; kk++) {
            float4 a4 = *(const float4*)&sKP[kk * 68 + ty * 4];
            float4 v4 = *(const float4*)&sV[kk * 68 + tx * 4];
            float a[4] = {a4.x, a4.y, a4.z, a4.w};
            float vv[4] = {v4.x, v4.y, v4.z, v4.w};
            #pragma unroll
            for (int i = 0; i < 4; i++)
                #pragma unroll
                for (int j = 0; j < 4; j++)
                    acc[i][j] = fmaf(a[i], vv[j], acc[i][j]);
        }
    }
    __syncthreads();   // last row_l update visible to all

    float* obase = g_attn + ((size_t)(b * S_ + qb * 64) * H_ + h) * 64;
    #pragma unroll
    for (int i = 0; i < 4; i++) {
        int r = ty * 4 + i;
        float inv = 1.f / row_l[r];
        float4 o;
        o.x = acc[i][0] * inv; o.y = acc[i][1] * inv;
        o.z = acc[i][2] * inv; o.w = acc[i][3] * inv;
        *(float4*)(obase + (size_t)r * 2048 + tx * 4) = o;
    }
}

// ---------------------------------------------------------------------------
extern "C" void kernel_launch(void* const* d_in, const int* in_sizes, int n_in,
                              void* d_out, int out_size)
{
    (void)in_sizes; (void)n_in; (void)out_size;
    const float* x   = (const float*)d_in[0];
    const float* cb  = (const float*)d_in[1];
    const float* sb  = (const float*)d_in[2];
    const float* Wq  = (const float*)d_in[3];
    const float* Wk  = (const float*)d_in[4];
    const float* Wv  = (const float*)d_in[5];
    const float* Wo  = (const float*)d_in[6];
    float* out = (float*)d_out;

    const int FLASH_SMEM = 3 * 64 * 68 * 4;   // 52224 B > 48K -> opt-in
    cudaFuncSetAttribute(flash_kernel,
                         cudaFuncAttributeMaxDynamicSharedMemorySize, FLASH_SMEM);

    dim3 gq(3072 / 128, 4096 / 128);
    qkv_gemm_kernel<<<gq, 256>>>(x, Wq, Wk, Wv);

    rope_kernel<<<(B_ * S_ * H_ * 32 + 255) / 256, 256>>>(cb, sb, 0);
    rope_kernel<<<(B_ * S_ * KVH_ * 32 + 255) / 256, 256>>>(cb, sb, 1);

    flash_kernel<<<dim3(S_ / 64, H_, B_), 256, FLASH_SMEM>>>();

    dim3 go(2048 / 128, 4096 / 128);
    out_gemm_kernel<<<go, 256>>>(Wo, out);
}

// round 3
// speedup vs baseline: 1.5224x; 1.5224x over previous
#include <cuda_runtime.h>
#include <cstdint>

#define B_   4
#define S_   1024
#define D_   2048
#define H_   32
#define KVH_ 8
#define HD_  64

// ---------------- device scratch (allocation-free rule) ----------------
__device__ float g_q[B_ * S_ * H_ * HD_];      // [4096, 2048]
__device__ float g_k[B_ * S_ * KVH_ * HD_];    // [4096, 512]
__device__ float g_v[B_ * S_ * KVH_ * HD_];    // [4096, 512]
__device__ float g_attn[B_ * S_ * H_ * HD_];   // [4096, 2048]
__device__ float g_WqT[2048 * 2048];           // Wq^T  [N=2048][K=2048]
__device__ float g_WkT[512 * 2048];
__device__ float g_WvT[512 * 2048];
__device__ float g_WoT[2048 * 2048];

__device__ __forceinline__ float tf32r(float x) {
    float r; asm("cvt.rna.tf32.f32 %0, %1;" : "=f"(r) : "f"(x)); return r;
}
__device__ __forceinline__ float4 tf32r4(float4 v) {
    v.x = tf32r(v.x); v.y = tf32r(v.y); v.z = tf32r(v.z); v.w = tf32r(v.w);
    return v;
}
__device__ __forceinline__ void mma_tf32(float* d, const uint32_t* a, const uint32_t* b) {
    asm volatile(
        "mma.sync.aligned.m16n8k8.row.col.f32.tf32.tf32.f32 "
        "{%0,%1,%2,%3}, {%4,%5,%6,%7}, {%8,%9}, {%0,%1,%2,%3};"
        : "+f"(d[0]), "+f"(d[1]), "+f"(d[2]), "+f"(d[3])
        : "r"(a[0]), "r"(a[1]), "r"(a[2]), "r"(a[3]), "r"(b[0]), "r"(b[1]));
}

// ---------------------------------------------------------------------------
// tf32 mma.sync GEMM: CTA = 128x128 tile, K = 2048
// A  [*,2048] row-major rows row0..row0+127
// BT [*,2048] row-major (W^T) rows 0..127 of the selected column block
// ---------------------------------------------------------------------------
__device__ __forceinline__ void gemm128_mma(
    const float* __restrict__ A, const float* __restrict__ BT,
    float* __restrict__ C, int ldc, int row0, int ccol0)
{
    __shared__ __align__(16) float As[2][128][20];   // [m][k] pad 20
    __shared__ __align__(16) float Bs[2][16][136];   // [k][n] pad 136

    const int tid  = threadIdx.x;            // 256
    const int wid  = tid >> 5, lane = tid & 31;
    const int g    = lane >> 2, c = lane & 3;
    const int wm   = (wid & 1) * 64;
    const int wn   = (wid >> 1) * 32;

    const int lm   = tid >> 1;               // 0..127 load row
    const int kofs = (tid & 1) * 8;          // float4 pair at k+0/k+4 or k+8/k+12

    float acc[4][4][4];
    #pragma unroll
    for (int mt = 0; mt < 4; mt++)
        #pragma unroll
        for (int nt = 0; nt < 4; nt++)
            #pragma unroll
            for (int e = 0; e < 4; e++) acc[mt][nt][e] = 0.f;

    const float* arow = A  + (size_t)(row0 + lm) * 2048 + kofs;
    const float* brow = BT + (size_t)lm * 2048 + kofs;

    float4 pa0, pa1, pb0, pb1;
    pa0 = tf32r4(*(const float4*)(arow + 0));
    pa1 = tf32r4(*(const float4*)(arow + 4));
    pb0 = tf32r4(*(const float4*)(brow + 0));
    pb1 = tf32r4(*(const float4*)(brow + 4));

    int buf = 0;
    // store stage 0
    *(float4*)&As[0][lm][kofs + 0] = pa0;
    *(float4*)&As[0][lm][kofs + 4] = pa1;
    {
        const float* e0 = (const float*)&pb0;
        const float* e1 = (const float*)&pb1;
        #pragma unroll
        for (int e = 0; e < 4; e++) Bs[0][kofs + e][lm]     = e0[e];
        #pragma unroll
        for (int e = 0; e < 4; e++) Bs[0][kofs + 4 + e][lm] = e1[e];
    }
    __syncthreads();

    for (int i = 0; i < 128; ++i) {
        if (i < 127) {
            const float* ap = arow + (i + 1) * 16;
            const float* bp = brow + (i + 1) * 16;
            pa0 = tf32r4(*(const float4*)(ap + 0));
            pa1 = tf32r4(*(const float4*)(ap + 4));
            pb0 = tf32r4(*(const float4*)(bp + 0));
            pb1 = tf32r4(*(const float4*)(bp + 4));
        }

        #pragma unroll
        for (int ks = 0; ks < 16; ks += 8) {
            uint32_t af[4][4];
            #pragma unroll
            for (int mt = 0; mt < 4; mt++) {
                const float* ap = &As[buf][wm + mt * 16 + g][ks + c];
                af[mt][0] = __float_as_uint(ap[0]);
                af[mt][1] = __float_as_uint(ap[8 * 20]);
                af[mt][2] = __float_as_uint(ap[4]);
                af[mt][3] = __float_as_uint(ap[8 * 20 + 4]);
            }
            uint32_t bfr[4][2];
            #pragma unroll
            for (int nt = 0; nt < 4; nt++) {
                bfr[nt][0] = __float_as_uint(Bs[buf][ks + c][wn + nt * 8 + g]);
                bfr[nt][1] = __float_as_uint(Bs[buf][ks + c + 4][wn + nt * 8 + g]);
            }
            #pragma unroll
            for (int mt = 0; mt < 4; mt++)
                #pragma unroll
                for (int nt = 0; nt < 4; nt++)
                    mma_tf32(acc[mt][nt], af[mt], bfr[nt]);
        }

        if (i < 127) {
            int nb = buf ^ 1;
            *(float4*)&As[nb][lm][kofs + 0] = pa0;
            *(float4*)&As[nb][lm][kofs + 4] = pa1;
            const float* e0 = (const float*)&pb0;
            const float* e1 = (const float*)&pb1;
            #pragma unroll
            for (int e = 0; e < 4; e++) Bs[nb][kofs + e][lm]     = e0[e];
            #pragma unroll
            for (int e = 0; e < 4; e++) Bs[nb][kofs + 4 + e][lm] = e1[e];
            __syncthreads();
            buf = nb;
        }
    }

    #pragma unroll
    for (int mt = 0; mt < 4; mt++) {
        int r = row0 + wm + mt * 16 + g;
        #pragma unroll
        for (int nt = 0; nt < 4; nt++) {
            int col = ccol0 + wn + nt * 8 + 2 * c;
            float2 lo = make_float2(acc[mt][nt][0], acc[mt][nt][1]);
            float2 hi = make_float2(acc[mt][nt][2], acc[mt][nt][3]);
            *(float2*)&C[(size_t)r * ldc + col]       = lo;
            *(float2*)&C[(size_t)(r + 8) * ldc + col] = hi;
        }
    }
}

__global__ __launch_bounds__(256) void qkv_gemm_tc(const float* __restrict__ X)
{
    int col0 = blockIdx.x * 128, row0 = blockIdx.y * 128;
    const float* BT; float* C; int ldc, ccol0;
    if (col0 < 2048)      { BT = g_WqT + (size_t)col0 * 2048;          C = g_q; ldc = 2048; ccol0 = col0; }
    else if (col0 < 2560) { BT = g_WkT + (size_t)(col0 - 2048) * 2048; C = g_k; ldc = 512;  ccol0 = col0 - 2048; }
    else                  { BT = g_WvT + (size_t)(col0 - 2560) * 2048; C = g_v; ldc = 512;  ccol0 = col0 - 2560; }
    gemm128_mma(X, BT, C, ldc, row0, ccol0);
}

__global__ __launch_bounds__(256) void out_gemm_tc(float* __restrict__ out)
{
    int col0 = blockIdx.x * 128, row0 = blockIdx.y * 128;
    gemm128_mma(g_attn, g_WoT + (size_t)col0 * 2048, out, 2048, row0, col0);
}

// ---------------------------------------------------------------------------
__global__ void transpose_kernel(const float* __restrict__ src,
                                 float* __restrict__ dst, int rows, int cols)
{
    __shared__ float t[32][33];
    int bx = blockIdx.x * 32, by = blockIdx.y * 32;
    int tx = threadIdx.x, ty = threadIdx.y;    // 32 x 8
    #pragma unroll
    for (int j = 0; j < 32; j += 8)
        t[ty + j][tx] = src[(size_t)(by + ty + j) * cols + bx + tx];
    __syncthreads();
    #pragma unroll
    for (int j = 0; j < 32; j += 8)
        dst[(size_t)(bx + ty + j) * rows + by + tx] = t[tx][ty + j];
}

// ---------------------------------------------------------------------------
__global__ void rope_kernel(const float* __restrict__ cosb,
                            const float* __restrict__ sinb, int which)
{
    float* buf = which ? g_k : g_q;
    int nh = which ? KVH_ : H_;
    int idx = blockIdx.x * blockDim.x + threadIdx.x;
    int total = B_ * S_ * nh * 32;
    if (idx >= total) return;
    int d = idx & 31;
    int h = (idx >> 5) % nh;
    int s = (idx / (32 * nh)) % S_;
    int b = idx / (32 * nh * S_);
    float* row = buf + (((size_t)(b * S_ + s)) * nh + h) * 64;
    float c1 = cosb[s * 64 + d],      s1 = sinb[s * 64 + d];
    float c2 = cosb[s * 64 + d + 32], s2 = sinb[s * 64 + d + 32];
    float x1 = row[d], x2 = row[d + 32];
    row[d]      = x1 * c1 - x2 * s1;
    row[d + 32] = x2 * c2 + x1 * s2;
}

// ---------------------------------------------------------------------------
// Flash attention fp32 (unchanged)
// ---------------------------------------------------------------------------
__global__ __launch_bounds__(256) void flash_kernel()
{
    extern __shared__ __align__(16) float sm[];
    float* sQt = sm;
    float* sKP = sm + 64 * 68;
    float* sV  = sm + 2 * 64 * 68;

    __shared__ float red[64][17];
    __shared__ float row_m[64], row_l[64], row_al[64];

    const int tid = threadIdx.x;
    const int tx = tid & 15, ty = tid >> 4;
    const int qb = blockIdx.x, h = blockIdx.y, b = blockIdx.z;
    const int kvh = h >> 2;

    const float* qbase = g_q + ((size_t)(b * S_ + qb * 64) * H_ + h) * 64;

    for (int t = tid; t < 1024; t += 256) {
        int r = t >> 4, d4 = t & 15;
        float4 v4 = *(const float4*)(qbase + (size_t)r * 2048 + d4 * 4);
        sQt[(d4 * 4 + 0) * 68 + r] = v4.x * 0.125f;
        sQt[(d4 * 4 + 1) * 68 + r] = v4.y * 0.125f;
        sQt[(d4 * 4 + 2) * 68 + r] = v4.z * 0.125f;
        sQt[(d4 * 4 + 3) * 68 + r] = v4.w * 0.125f;
    }
    if (tid < 64) { row_m[tid] = -3.0e38f; row_l[tid] = 0.f; }

    float acc[4][4];
    #pragma unroll
    for (int i = 0; i < 4; i++)
        #pragma unroll
        for (int j = 0; j < 4; j++) acc[i][j] = 0.f;

    for (int j0 = 0; j0 < S_; j0 += 64) {
        __syncthreads();
        const float* kbase = g_k + ((size_t)(b * S_ + j0) * KVH_ + kvh) * 64;
        const float* vbase = g_v + ((size_t)(b * S_ + j0) * KVH_ + kvh) * 64;
        for (int t = tid; t < 1024; t += 256) {
            int r = t >> 4, d4 = t & 15;
            float4 kv = *(const float4*)(kbase + (size_t)r * 512 + d4 * 4);
            sKP[(d4 * 4 + 0) * 68 + r] = kv.x;
            sKP[(d4 * 4 + 1) * 68 + r] = kv.y;
            sKP[(d4 * 4 + 2) * 68 + r] = kv.z;
            sKP[(d4 * 4 + 3) * 68 + r] = kv.w;
            float4 vv = *(const float4*)(vbase + (size_t)r * 512 + d4 * 4);
            *(float4*)&sV[r * 68 + d4 * 4] = vv;
        }
        __syncthreads();

        float s[4][4];
        #pragma unroll
        for (int i = 0; i < 4; i++)
            #pragma unroll
            for (int j = 0; j < 4; j++) s[i][j] = 0.f;
        #pragma unroll
        for (int d = 0; d < 64; d++) {
            float4 a4 = *(const float4*)&sQt[d * 68 + ty * 4];
            float4 b4 = *(const float4*)&sKP[d * 68 + tx * 4];
            float a[4] = {a4.x, a4.y, a4.z, a4.w};
            float bb[4] = {b4.x, b4.y, b4.z, b4.w};
            #pragma unroll
            for (int i = 0; i < 4; i++)
                #pragma unroll
                for (int j = 0; j < 4; j++)
                    s[i][j] = fmaf(a[i], bb[j], s[i][j]);
        }

        #pragma unroll
        for (int i = 0; i < 4; i++) {
            float m = fmaxf(fmaxf(s[i][0], s[i][1]), fmaxf(s[i][2], s[i][3]));
            red[ty * 4 + i][tx] = m;
        }
        __syncthreads();
        if (tid < 64) {
            float tm = red[tid][0];
            #pragma unroll
            for (int k = 1; k < 16; k++) tm = fmaxf(tm, red[tid][k]);
            float mo = row_m[tid];
            float mn = fmaxf(mo, tm);
            row_al[tid] = __expf(mo - mn);
            row_m[tid]  = mn;
        }
        __syncthreads();

        #pragma unroll
        for (int i = 0; i < 4; i++) {
            int r = ty * 4 + i;
            float mn = row_m[r], al = row_al[r];
            float sum = 0.f;
            #pragma unroll
            for (int j = 0; j < 4; j++) {
                float p = __expf(s[i][j] - mn);
                sum += p;
                acc[i][j] *= al;
                sKP[(tx * 4 + j) * 68 + r] = p;
            }
            red[r][tx] = sum;
        }
        __syncthreads();
        if (tid < 64) {
            float sum = 0.f;
            #pragma unroll
            for (int k = 0; k < 16; k++) sum += red[tid][k];
            row_l[tid] = row_l[tid] * row_al[tid] + sum;
        }

        #pragma unroll
        for (int kk = 0; kk < 64; kk++) {
            float4 a4 = *(const float4*)&sKP[kk * 68 + ty * 4];
            float4 v4 = *(const float4*)&sV[kk * 68 + tx * 4];
            float a[4] = {a4.x, a4.y, a4.z, a4.w};
            float vv[4] = {v4.x, v4.y, v4.z, v4.w};
            #pragma unroll
            for (int i = 0; i < 4; i++)
                #pragma unroll
                for (int j = 0; j < 4; j++)
                    acc[i][j] = fmaf(a[i], vv[j], acc[i][j]);
        }
    }
    __syncthreads();

    float* obase = g_attn + ((size_t)(b * S_ + qb * 64) * H_ + h) * 64;
    #pragma unroll
    for (int i = 0; i < 4; i++) {
        int r = ty * 4 + i;
        float inv = 1.f / row_l[r];
        float4 o;
        o.x = acc[i][0] * inv; o.y = acc[i][1] * inv;
        o.z = acc[i][2] * inv; o.w = acc[i][3] * inv;
        *(float4*)(obase + (size_t)r * 2048 + tx * 4) = o;
    }
}

// ---------------------------------------------------------------------------
extern "C" void kernel_launch(void* const* d_in, const int* in_sizes, int n_in,
                              void* d_out, int out_size)
{
    (void)in_sizes; (void)n_in; (void)out_size;
    const float* x   = (const float*)d_in[0];
    const float* cb  = (const float*)d_in[1];
    const float* sb  = (const float*)d_in[2];
    const float* Wq  = (const float*)d_in[3];
    const float* Wk  = (const float*)d_in[4];
    const float* Wv  = (const float*)d_in[5];
    const float* Wo  = (const float*)d_in[6];
    float* out = (float*)d_out;

    const int FLASH_SMEM = 3 * 64 * 68 * 4;         // 52224 B
    cudaFuncSetAttribute(flash_kernel, cudaFuncAttributeMaxDynamicSharedMemorySize, FLASH_SMEM);

    float* wqT; float* wkT; float* wvT; float* woT;
    cudaGetSymbolAddress((void**)&wqT, g_WqT);
    cudaGetSymbolAddress((void**)&wkT, g_WkT);
    cudaGetSymbolAddress((void**)&wvT, g_WvT);
    cudaGetSymbolAddress((void**)&woT, g_WoT);

    dim3 tb(32, 8);
    transpose_kernel<<<dim3(2048 / 32, 2048 / 32), tb>>>(Wq, wqT, 2048, 2048);
    transpose_kernel<<<dim3(512  / 32, 2048 / 32), tb>>>(Wk, wkT, 2048, 512);
    transpose_kernel<<<dim3(512  / 32, 2048 / 32), tb>>>(Wv, wvT, 2048, 512);
    transpose_kernel<<<dim3(2048 / 32, 2048 / 32), tb>>>(Wo, woT, 2048, 2048);

    qkv_gemm_tc<<<dim3(3072 / 128, 4096 / 128), 256>>>(x);

    rope_kernel<<<(B_ * S_ * H_ * 32 + 255) / 256, 256>>>(cb, sb, 0);
    rope_kernel<<<(B_ * S_ * KVH_ * 32 + 255) / 256, 256>>>(cb, sb, 1);

    flash_kernel<<<dim3(S_ / 64, H_, B_), 256, FLASH_SMEM>>>();

    out_gemm_tc<<<dim3(2048 / 128, 4096 / 128), 256>>>(out);
}

// round 4
// speedup vs baseline: 2.3297x; 1.5302x over previous
#include <cuda_runtime.h>
#include <cstdint>

#define B_   4
#define S_   1024
#define D_   2048
#define H_   32
#define KVH_ 8
#define HD_  64

// ---------------- device scratch ----------------
__device__ float g_q[B_ * S_ * H_ * HD_];
__device__ float g_k[B_ * S_ * KVH_ * HD_];
__device__ float g_v[B_ * S_ * KVH_ * HD_];
__device__ float g_attn[B_ * S_ * H_ * HD_];
__device__ float g_WqT[2048 * 2048];
__device__ float g_WkT[512 * 2048];
__device__ float g_WvT[512 * 2048];
__device__ float g_WoT[2048 * 2048];

__device__ __forceinline__ float tf32r(float x) {
    float r; asm("cvt.rna.tf32.f32 %0, %1;" : "=f"(r) : "f"(x)); return r;
}
__device__ __forceinline__ float4 tf32r4(float4 v) {
    v.x = tf32r(v.x); v.y = tf32r(v.y); v.z = tf32r(v.z); v.w = tf32r(v.w);
    return v;
}
__device__ __forceinline__ void mma_tf32(float* d, const uint32_t* a, const uint32_t* b) {
    asm volatile(
        "mma.sync.aligned.m16n8k8.row.col.f32.tf32.tf32.f32 "
        "{%0,%1,%2,%3}, {%4,%5,%6,%7}, {%8,%9}, {%0,%1,%2,%3};"
        : "+f"(d[0]), "+f"(d[1]), "+f"(d[2]), "+f"(d[3])
        : "r"(a[0]), "r"(a[1]), "r"(a[2]), "r"(a[3]), "r"(b[0]), "r"(b[1]));
}
__device__ __forceinline__ void mma_tf32f(float* d, const float* a, const float* b) {
    asm volatile(
        "mma.sync.aligned.m16n8k8.row.col.f32.tf32.tf32.f32 "
        "{%0,%1,%2,%3}, {%4,%5,%6,%7}, {%8,%9}, {%0,%1,%2,%3};"
        : "+f"(d[0]), "+f"(d[1]), "+f"(d[2]), "+f"(d[3])
        : "r"(__float_as_uint(a[0])), "r"(__float_as_uint(a[1])),
          "r"(__float_as_uint(a[2])), "r"(__float_as_uint(a[3])),
          "r"(__float_as_uint(b[0])), "r"(__float_as_uint(b[1])));
}

// ---------------------------------------------------------------------------
// tf32 mma.sync GEMM (unchanged from R3): CTA = 128x128 tile, K = 2048
// ---------------------------------------------------------------------------
__device__ __forceinline__ void gemm128_mma(
    const float* __restrict__ A, const float* __restrict__ BT,
    float* __restrict__ C, int ldc, int row0, int ccol0)
{
    __shared__ __align__(16) float As[2][128][20];
    __shared__ __align__(16) float Bs[2][16][136];

    const int tid  = threadIdx.x;
    const int wid  = tid >> 5, lane = tid & 31;
    const int g    = lane >> 2, c = lane & 3;
    const int wm   = (wid & 1) * 64;
    const int wn   = (wid >> 1) * 32;
    const int lm   = tid >> 1;
    const int kofs = (tid & 1) * 8;

    float acc[4][4][4];
    #pragma unroll
    for (int mt = 0; mt < 4; mt++)
        #pragma unroll
        for (int nt = 0; nt < 4; nt++)
            #pragma unroll
            for (int e = 0; e < 4; e++) acc[mt][nt][e] = 0.f;

    const float* arow = A  + (size_t)(row0 + lm) * 2048 + kofs;
    const float* brow = BT + (size_t)lm * 2048 + kofs;

    float4 pa0 = tf32r4(*(const float4*)(arow + 0));
    float4 pa1 = tf32r4(*(const float4*)(arow + 4));
    float4 pb0 = tf32r4(*(const float4*)(brow + 0));
    float4 pb1 = tf32r4(*(const float4*)(brow + 4));

    int buf = 0;
    *(float4*)&As[0][lm][kofs + 0] = pa0;
    *(float4*)&As[0][lm][kofs + 4] = pa1;
    {
        const float* e0 = (const float*)&pb0;
        const float* e1 = (const float*)&pb1;
        #pragma unroll
        for (int e = 0; e < 4; e++) Bs[0][kofs + e][lm]     = e0[e];
        #pragma unroll
        for (int e = 0; e < 4; e++) Bs[0][kofs + 4 + e][lm] = e1[e];
    }
    __syncthreads();

    for (int i = 0; i < 128; ++i) {
        if (i < 127) {
            const float* ap = arow + (i + 1) * 16;
            const float* bp = brow + (i + 1) * 16;
            pa0 = tf32r4(*(const float4*)(ap + 0));
            pa1 = tf32r4(*(const float4*)(ap + 4));
            pb0 = tf32r4(*(const float4*)(bp + 0));
            pb1 = tf32r4(*(const float4*)(bp + 4));
        }
        #pragma unroll
        for (int ks = 0; ks < 16; ks += 8) {
            uint32_t af[4][4];
            #pragma unroll
            for (int mt = 0; mt < 4; mt++) {
                const float* ap = &As[buf][wm + mt * 16 + g][ks + c];
                af[mt][0] = __float_as_uint(ap[0]);
                af[mt][1] = __float_as_uint(ap[8 * 20]);
                af[mt][2] = __float_as_uint(ap[4]);
                af[mt][3] = __float_as_uint(ap[8 * 20 + 4]);
            }
            uint32_t bfr[4][2];
            #pragma unroll
            for (int nt = 0; nt < 4; nt++) {
                bfr[nt][0] = __float_as_uint(Bs[buf][ks + c][wn + nt * 8 + g]);
                bfr[nt][1] = __float_as_uint(Bs[buf][ks + c + 4][wn + nt * 8 + g]);
            }
            #pragma unroll
            for (int mt = 0; mt < 4; mt++)
                #pragma unroll
                for (int nt = 0; nt < 4; nt++)
                    mma_tf32(acc[mt][nt], af[mt], bfr[nt]);
        }
        if (i < 127) {
            int nb = buf ^ 1;
            *(float4*)&As[nb][lm][kofs + 0] = pa0;
            *(float4*)&As[nb][lm][kofs + 4] = pa1;
            const float* e0 = (const float*)&pb0;
            const float* e1 = (const float*)&pb1;
            #pragma unroll
            for (int e = 0; e < 4; e++) Bs[nb][kofs + e][lm]     = e0[e];
            #pragma unroll
            for (int e = 0; e < 4; e++) Bs[nb][kofs + 4 + e][lm] = e1[e];
            __syncthreads();
            buf = nb;
        }
    }

    #pragma unroll
    for (int mt = 0; mt < 4; mt++) {
        int r = row0 + wm + mt * 16 + g;
        #pragma unroll
        for (int nt = 0; nt < 4; nt++) {
            int col = ccol0 + wn + nt * 8 + 2 * c;
            *(float2*)&C[(size_t)r * ldc + col]       = make_float2(acc[mt][nt][0], acc[mt][nt][1]);
            *(float2*)&C[(size_t)(r + 8) * ldc + col] = make_float2(acc[mt][nt][2], acc[mt][nt][3]);
        }
    }
}

__global__ __launch_bounds__(256) void qkv_gemm_tc(const float* __restrict__ X)
{
    int col0 = blockIdx.x * 128, row0 = blockIdx.y * 128;
    const float* BT; float* C; int ldc, ccol0;
    if (col0 < 2048)      { BT = g_WqT + (size_t)col0 * 2048;          C = g_q; ldc = 2048; ccol0 = col0; }
    else if (col0 < 2560) { BT = g_WkT + (size_t)(col0 - 2048) * 2048; C = g_k; ldc = 512;  ccol0 = col0 - 2048; }
    else                  { BT = g_WvT + (size_t)(col0 - 2560) * 2048; C = g_v; ldc = 512;  ccol0 = col0 - 2560; }
    gemm128_mma(X, BT, C, ldc, row0, ccol0);
}

__global__ __launch_bounds__(256) void out_gemm_tc(float* __restrict__ out)
{
    int col0 = blockIdx.x * 128, row0 = blockIdx.y * 128;
    gemm128_mma(g_attn, g_WoT + (size_t)col0 * 2048, out, 2048, row0, col0);
}

// ---------------------------------------------------------------------------
__global__ void transpose_kernel(const float* __restrict__ src,
                                 float* __restrict__ dst, int rows, int cols)
{
    __shared__ float t[32][33];
    int bx = blockIdx.x * 32, by = blockIdx.y * 32;
    int tx = threadIdx.x, ty = threadIdx.y;
    #pragma unroll
    for (int j = 0; j < 32; j += 8)
        t[ty + j][tx] = src[(size_t)(by + ty + j) * cols + bx + tx];
    __syncthreads();
    #pragma unroll
    for (int j = 0; j < 32; j += 8)
        dst[(size_t)(bx + ty + j) * rows + by + tx] = t[tx][ty + j];
}

// ---------------------------------------------------------------------------
__global__ void rope_kernel(const float* __restrict__ cosb,
                            const float* __restrict__ sinb, int which)
{
    float* buf = which ? g_k : g_q;
    int nh = which ? KVH_ : H_;
    int idx = blockIdx.x * blockDim.x + threadIdx.x;
    int total = B_ * S_ * nh * 32;
    if (idx >= total) return;
    int d = idx & 31;
    int h = (idx >> 5) % nh;
    int s = (idx / (32 * nh)) % S_;
    int b = idx / (32 * nh * S_);
    float* row = buf + (((size_t)(b * S_ + s)) * nh + h) * 64;
    float c1 = cosb[s * 64 + d],      s1 = sinb[s * 64 + d];
    float c2 = cosb[s * 64 + d + 32], s2 = sinb[s * 64 + d + 32];
    float x1 = row[d], x2 = row[d + 32];
    row[d]      = x1 * c1 - x2 * s1;
    row[d + 32] = x2 * c2 + x1 * s2;
}

// ---------------------------------------------------------------------------
// Flash attention, tf32 mma.sync. Block = 128 q-rows x (head, batch).
// 8 warps; warp w owns rows w*16..w*16+15 (full rows -> in-quad softmax only).
// ---------------------------------------------------------------------------
__global__ __launch_bounds__(256) void flash_mma_kernel()
{
    __shared__ __align__(16) float sK[64][68];   // [key][dim]  (4g+c banks)
    __shared__ __align__(16) float sV[64][72];   // [key][dim]  (8c+g banks)

    const int tid = threadIdx.x;
    const int wid = tid >> 5, lane = tid & 31;
    const int g = lane >> 2, c = lane & 3;
    const int qb = blockIdx.x, h = blockIdx.y, b = blockIdx.z;
    const int kvh = h >> 2;

    // Q fragments (rows wid*16+g / +8), pre-scaled, tf32-rounded
    const float* qbase = g_q + ((size_t)(b * S_ + qb * 128 + wid * 16) * H_ + h) * 64;
    float qa[8][4];
    #pragma unroll
    for (int kc = 0; kc < 8; kc++) {
        qa[kc][0] = tf32r(qbase[(size_t)g * 2048       + kc * 8 + c]     * 0.125f);
        qa[kc][1] = tf32r(qbase[(size_t)(g + 8) * 2048 + kc * 8 + c]     * 0.125f);
        qa[kc][2] = tf32r(qbase[(size_t)g * 2048       + kc * 8 + c + 4] * 0.125f);
        qa[kc][3] = tf32r(qbase[(size_t)(g + 8) * 2048 + kc * 8 + c + 4] * 0.125f);
    }

    float o[8][4];
    #pragma unroll
    for (int dt = 0; dt < 8; dt++)
        #pragma unroll
        for (int e = 0; e < 4; e++) o[dt][e] = 0.f;
    float m0 = -1.0e30f, m1 = -1.0e30f, l0 = 0.f, l1 = 0.f;

    for (int j0 = 0; j0 < S_; j0 += 64) {
        __syncthreads();   // protect previous-iteration smem reads
        const float* kbase = g_k + ((size_t)(b * S_ + j0) * KVH_ + kvh) * 64;
        const float* vbase = g_v + ((size_t)(b * S_ + j0) * KVH_ + kvh) * 64;
        #pragma unroll
        for (int u = 0; u < 4; u++) {
            int idx = tid + u * 256;
            int r = idx >> 4, c4 = idx & 15;
            float4 kv = tf32r4(*(const float4*)(kbase + (size_t)r * 512 + c4 * 4));
            *(float4*)&sK[r][c4 * 4] = kv;
            float4 vv = tf32r4(*(const float4*)(vbase + (size_t)r * 512 + c4 * 4));
            *(float4*)&sV[r][c4 * 4] = vv;
        }
        __syncthreads();

        // S = Q @ K^T : 8 n-tiles (keys) x 8 k-chunks (dims)
        float s[8][4];
        #pragma unroll
        for (int nt = 0; nt < 8; nt++)
            #pragma unroll
            for (int e = 0; e < 4; e++) s[nt][e] = 0.f;
        #pragma unroll
        for (int nt = 0; nt < 8; nt++) {
            #pragma unroll
            for (int kc = 0; kc < 8; kc++) {
                float bf[2];
                bf[0] = sK[nt * 8 + g][kc * 8 + c];
                bf[1] = sK[nt * 8 + g][kc * 8 + c + 4];
                mma_tf32f(s[nt], qa[kc], bf);
            }
        }

        // row max (rows g -> elems 0,1 ; rows g+8 -> elems 2,3), quad-reduce
        float tm0 = -1.0e30f, tm1 = -1.0e30f;
        #pragma unroll
        for (int nt = 0; nt < 8; nt++) {
            tm0 = fmaxf(tm0, fmaxf(s[nt][0], s[nt][1]));
            tm1 = fmaxf(tm1, fmaxf(s[nt][2], s[nt][3]));
        }
        tm0 = fmaxf(tm0, __shfl_xor_sync(0xffffffffu, tm0, 1));
        tm0 = fmaxf(tm0, __shfl_xor_sync(0xffffffffu, tm0, 2));
        tm1 = fmaxf(tm1, __shfl_xor_sync(0xffffffffu, tm1, 1));
        tm1 = fmaxf(tm1, __shfl_xor_sync(0xffffffffu, tm1, 2));

        float nm0 = fmaxf(m0, tm0), nm1 = fmaxf(m1, tm1);
        float al0 = __expf(m0 - nm0), al1 = __expf(m1 - nm1);
        m0 = nm0; m1 = nm1;

        float sum0 = 0.f, sum1 = 0.f;
        #pragma unroll
        for (int nt = 0; nt < 8; nt++) {
            s[nt][0] = tf32r(__expf(s[nt][0] - nm0));
            s[nt][1] = tf32r(__expf(s[nt][1] - nm0));
            s[nt][2] = tf32r(__expf(s[nt][2] - nm1));
            s[nt][3] = tf32r(__expf(s[nt][3] - nm1));
            sum0 += s[nt][0] + s[nt][1];
            sum1 += s[nt][2] + s[nt][3];
        }
        sum0 += __shfl_xor_sync(0xffffffffu, sum0, 1);
        sum0 += __shfl_xor_sync(0xffffffffu, sum0, 2);
        sum1 += __shfl_xor_sync(0xffffffffu, sum1, 1);
        sum1 += __shfl_xor_sync(0xffffffffu, sum1, 2);
        l0 = l0 * al0 + sum0;
        l1 = l1 * al1 + sum1;

        #pragma unroll
        for (int dt = 0; dt < 8; dt++) {
            o[dt][0] *= al0; o[dt][1] *= al0;
            o[dt][2] *= al1; o[dt][3] *= al1;
        }

        // O += P @ V. A-frag for k-chunk kc built from s[kc] via quad shuffles.
        const int qbase_l = lane & ~3;
        const int src0 = qbase_l + (c >> 1);
        const int src1 = src0 + 2;
        const int e = c & 1;
        #pragma unroll
        for (int kc = 0; kc < 8; kc++) {
            float t00 = __shfl_sync(0xffffffffu, s[kc][0], src0);
            float t01 = __shfl_sync(0xffffffffu, s[kc][1], src0);
            float t02 = __shfl_sync(0xffffffffu, s[kc][2], src0);
            float t03 = __shfl_sync(0xffffffffu, s[kc][3], src0);
            float t10 = __shfl_sync(0xffffffffu, s[kc][0], src1);
            float t11 = __shfl_sync(0xffffffffu, s[kc][1], src1);
            float t12 = __shfl_sync(0xffffffffu, s[kc][2], src1);
            float t13 = __shfl_sync(0xffffffffu, s[kc][3], src1);
            float a[4];
            a[0] = e ? t01 : t00;   // P[g][c]
            a[1] = e ? t03 : t02;   // P[g+8][c]
            a[2] = e ? t11 : t10;   // P[g][c+4]
            a[3] = e ? t13 : t12;   // P[g+8][c+4]
            #pragma unroll
            for (int dt = 0; dt < 8; dt++) {
                float bf[2];
                bf[0] = sV[kc * 8 + c][dt * 8 + g];
                bf[1] = sV[kc * 8 + c + 4][dt * 8 + g];
                mma_tf32f(o[dt], a, bf);
            }
        }
    }

    // write O / l
    float inv0 = 1.f / l0, inv1 = 1.f / l1;
    float* obase = g_attn + ((size_t)(b * S_ + qb * 128 + wid * 16) * H_ + h) * 64;
    #pragma unroll
    for (int dt = 0; dt < 8; dt++) {
        *(float2*)&obase[(size_t)g * 2048 + dt * 8 + 2 * c] =
            make_float2(o[dt][0] * inv0, o[dt][1] * inv0);
        *(float2*)&obase[(size_t)(g + 8) * 2048 + dt * 8 + 2 * c] =
            make_float2(o[dt][2] * inv1, o[dt][3] * inv1);
    }
}

// ---------------------------------------------------------------------------
extern "C" void kernel_launch(void* const* d_in, const int* in_sizes, int n_in,
                              void* d_out, int out_size)
{
    (void)in_sizes; (void)n_in; (void)out_size;
    const float* x   = (const float*)d_in[0];
    const float* cb  = (const float*)d_in[1];
    const float* sb  = (const float*)d_in[2];
    const float* Wq  = (const float*)d_in[3];
    const float* Wk  = (const float*)d_in[4];
    const float* Wv  = (const float*)d_in[5];
    const float* Wo  = (const float*)d_in[6];
    float* out = (float*)d_out;

    float* wqT; float* wkT; float* wvT; float* woT;
    cudaGetSymbolAddress((void**)&wqT, g_WqT);
    cudaGetSymbolAddress((void**)&wkT, g_WkT);
    cudaGetSymbolAddress((void**)&wvT, g_WvT);
    cudaGetSymbolAddress((void**)&woT, g_WoT);

    dim3 tb(32, 8);
    transpose_kernel<<<dim3(2048 / 32, 2048 / 32), tb>>>(Wq, wqT, 2048, 2048);
    transpose_kernel<<<dim3(512  / 32, 2048 / 32), tb>>>(Wk, wkT, 2048, 512);
    transpose_kernel<<<dim3(512  / 32, 2048 / 32), tb>>>(Wv, wvT, 2048, 512);
    transpose_kernel<<<dim3(2048 / 32, 2048 / 32), tb>>>(Wo, woT, 2048, 2048);

    qkv_gemm_tc<<<dim3(3072 / 128, 4096 / 128), 256>>>(x);

    rope_kernel<<<(B_ * S_ * H_ * 32 + 255) / 256, 256>>>(cb, sb, 0);
    rope_kernel<<<(B_ * S_ * KVH_ * 32 + 255) / 256, 256>>>(cb, sb, 1);

    flash_mma_kernel<<<dim3(S_ / 128, H_, B_), 256>>>();

    out_gemm_tc<<<dim3(2048 / 128, 4096 / 128), 256>>>(out);
}

// round 5
// speedup vs baseline: 2.8299x; 1.2147x over previous
#include <cuda_runtime.h>
#include <cstdint>

#define B_   4
#define S_   1024
#define D_   2048
#define H_   32
#define KVH_ 8
#define HD_  64

#define STAGES 4

// ---------------- device scratch ----------------
__device__ float g_q[B_ * S_ * H_ * HD_];
__device__ float g_k[B_ * S_ * KVH_ * HD_];
__device__ float g_v[B_ * S_ * KVH_ * HD_];
__device__ float g_attn[B_ * S_ * H_ * HD_];
__device__ float g_xr[B_ * S_ * D_];          // tf32-rounded X
__device__ float g_Wqr[2048 * 2048];          // tf32-rounded weights (NOT transposed)
__device__ float g_Wkr[2048 * 512];
__device__ float g_Wvr[2048 * 512];
__device__ float g_Wor[2048 * 2048];

__device__ __forceinline__ float tf32r(float x) {
    float r; asm("cvt.rna.tf32.f32 %0, %1;" : "=f"(r) : "f"(x)); return r;
}
__device__ __forceinline__ float4 tf32r4(float4 v) {
    v.x = tf32r(v.x); v.y = tf32r(v.y); v.z = tf32r(v.z); v.w = tf32r(v.w);
    return v;
}
__device__ __forceinline__ uint32_t smem_u32(const void* p) {
    uint32_t a;
    asm("{ .reg .u64 t; cvta.to.shared.u64 t, %1; cvt.u32.u64 %0, t; }"
        : "=r"(a) : "l"(p));
    return a;
}
__device__ __forceinline__ void cpa16(uint32_t dst, const void* src) {
    asm volatile("cp.async.cg.shared.global [%0], [%1], 16;" :: "r"(dst), "l"(src));
}
#define CP_COMMIT() asm volatile("cp.async.commit_group;" ::: "memory")
#define CP_WAIT(n)  asm volatile("cp.async.wait_group %0;" :: "n"(n) : "memory")

__device__ __forceinline__ void mma_tf32(float* d, const uint32_t* a, const uint32_t* b) {
    asm volatile(
        "mma.sync.aligned.m16n8k8.row.col.f32.tf32.tf32.f32 "
        "{%0,%1,%2,%3}, {%4,%5,%6,%7}, {%8,%9}, {%0,%1,%2,%3};"
        : "+f"(d[0]), "+f"(d[1]), "+f"(d[2]), "+f"(d[3])
        : "r"(a[0]), "r"(a[1]), "r"(a[2]), "r"(a[3]), "r"(b[0]), "r"(b[1]));
}
__device__ __forceinline__ void mma_tf32f(float* d, const float* a, const float* b) {
    asm volatile(
        "mma.sync.aligned.m16n8k8.row.col.f32.tf32.tf32.f32 "
        "{%0,%1,%2,%3}, {%4,%5,%6,%7}, {%8,%9}, {%0,%1,%2,%3};"
        : "+f"(d[0]), "+f"(d[1]), "+f"(d[2]), "+f"(d[3])
        : "r"(__float_as_uint(a[0])), "r"(__float_as_uint(a[1])),
          "r"(__float_as_uint(a[2])), "r"(__float_as_uint(a[3])),
          "r"(__float_as_uint(b[0])), "r"(__float_as_uint(b[1])));
}

// ---------------------------------------------------------------------------
// tf32-rounding elementwise pass (float4 grid-stride)
// ---------------------------------------------------------------------------
__global__ void round_kernel(const float* __restrict__ src,
                             float* __restrict__ dst, int n4)
{
    int i = blockIdx.x * blockDim.x + threadIdx.x;
    if (i < n4)
        *(float4*)(dst + i * 4) = tf32r4(*(const float4*)(src + i * 4));
}

// ---------------------------------------------------------------------------
// tf32 mma.sync GEMM, cp.async 4-stage pipeline. CTA = 128x128 tile, K=2048.
// A [*,2048] row-major (pre-rounded). W [2048][ldw] row-major (pre-rounded).
// ---------------------------------------------------------------------------
// stage sizes in floats
#define ASTG 2560   // 128 * 20
#define BSTG 2112   // 16 * 132

__device__ __forceinline__ void gemm128_cp(
    const float* __restrict__ A, const float* __restrict__ W,
    float* __restrict__ C, int ldw, int ldc, int row0, int wc0)
{
    extern __shared__ __align__(16) float sm[];
    float* As = sm;                       // [STAGES][128][20]
    float* Bs = sm + STAGES * ASTG;       // [STAGES][16][132]
    const uint32_t asb = smem_u32(As), bsb = smem_u32(Bs);

    const int tid  = threadIdx.x;
    const int wid  = tid >> 5, lane = tid & 31;
    const int g    = lane >> 2, c = lane & 3;
    const int wm   = (wid & 1) * 64;
    const int wn   = (wid >> 1) * 32;

    // cp.async load mapping: A 128x16 floats, B 16x128 floats, 32B per thread each
    const int arow = tid >> 1, aseg = (tid & 1) * 2;          // seg = float4 idx
    const int bk   = tid >> 4, bn   = (tid & 15) * 8;         // bn in floats
    const float* asrc = A + (size_t)(row0 + arow) * 2048 + aseg * 4;
    const float* bsrc = W + (size_t)bk * ldw + wc0 + bn;
    const uint32_t adst = asb + (arow * 20 + aseg * 4) * 4;
    const uint32_t bdst = bsb + (bk * 132 + bn) * 4;

    float acc[4][4][4];
    #pragma unroll
    for (int mt = 0; mt < 4; mt++)
        #pragma unroll
        for (int nt = 0; nt < 4; nt++)
            #pragma unroll
            for (int e = 0; e < 4; e++) acc[mt][nt][e] = 0.f;

    // prologue: issue stages 0..STAGES-2
    #pragma unroll
    for (int s = 0; s < STAGES - 1; s++) {
        const float* ap = asrc + s * 16;
        cpa16(adst + s * ASTG * 4,      ap);
        cpa16(adst + s * ASTG * 4 + 16, ap + 4);
        const float* bp = bsrc + (size_t)s * 16 * ldw;
        cpa16(bdst + s * BSTG * 4,      bp);
        cpa16(bdst + s * BSTG * 4 + 16, bp + 4);
        CP_COMMIT();
    }

    int buf = 0;
    for (int i = 0; i < 128; ++i) {
        CP_WAIT(STAGES - 2);
        __syncthreads();

        const float* Ab = As + buf * ASTG;
        const float* Bb = Bs + buf * BSTG;
        #pragma unroll
        for (int ks = 0; ks < 16; ks += 8) {
            uint32_t af[4][4];
            #pragma unroll
            for (int mt = 0; mt < 4; mt++) {
                const float* ap = &Ab[(wm + mt * 16 + g) * 20 + ks + c];
                af[mt][0] = __float_as_uint(ap[0]);
                af[mt][1] = __float_as_uint(ap[8 * 20]);
                af[mt][2] = __float_as_uint(ap[4]);
                af[mt][3] = __float_as_uint(ap[8 * 20 + 4]);
            }
            uint32_t bfr[4][2];
            #pragma unroll
            for (int nt = 0; nt < 4; nt++) {
                bfr[nt][0] = __float_as_uint(Bb[(ks + c) * 132     + wn + nt * 8 + g]);
                bfr[nt][1] = __float_as_uint(Bb[(ks + c + 4) * 132 + wn + nt * 8 + g]);
            }
            #pragma unroll
            for (int mt = 0; mt < 4; mt++)
                #pragma unroll
                for (int nt = 0; nt < 4; nt++)
                    mma_tf32(acc[mt][nt], af[mt], bfr[nt]);
        }

        int nk = i + STAGES - 1;        // next k-block to fetch
        if (nk < 128) {
            int s = nk % STAGES;
            const float* ap = asrc + nk * 16;
            cpa16(adst + s * ASTG * 4,      ap);
            cpa16(adst + s * ASTG * 4 + 16, ap + 4);
            const float* bp = bsrc + (size_t)nk * 16 * ldw;
            cpa16(bdst + s * BSTG * 4,      bp);
            cpa16(bdst + s * BSTG * 4 + 16, bp + 4);
        }
        CP_COMMIT();                    // empty groups on tail keep counts aligned
        buf = (buf + 1) % STAGES;
    }

    #pragma unroll
    for (int mt = 0; mt < 4; mt++) {
        int r = row0 + wm + mt * 16 + g;
        #pragma unroll
        for (int nt = 0; nt < 4; nt++) {
            int col = wc0 + wn + nt * 8 + 2 * c;
            *(float2*)&C[(size_t)r * ldc + col]       = make_float2(acc[mt][nt][0], acc[mt][nt][1]);
            *(float2*)&C[(size_t)(r + 8) * ldc + col] = make_float2(acc[mt][nt][2], acc[mt][nt][3]);
        }
    }
}

__global__ __launch_bounds__(256) void qkv_gemm_tc(const float* __restrict__ X)
{
    int col0 = blockIdx.x * 128, row0 = blockIdx.y * 128;
    const float* W; float* C; int ldw, ldc, wc0;
    if (col0 < 2048)      { W = g_Wqr; C = g_q; ldw = 2048; ldc = 2048; wc0 = col0; }
    else if (col0 < 2560) { W = g_Wkr; C = g_k; ldw = 512;  ldc = 512;  wc0 = col0 - 2048; }
    else                  { W = g_Wvr; C = g_v; ldw = 512;  ldc = 512;  wc0 = col0 - 2560; }
    gemm128_cp(X, W, C, ldw, ldc, row0, wc0);
}

__global__ __launch_bounds__(256) void out_gemm_tc(float* __restrict__ out)
{
    int col0 = blockIdx.x * 128, row0 = blockIdx.y * 128;
    gemm128_cp(g_attn, g_Wor, out, 2048, 2048, row0, col0);
}

// ---------------------------------------------------------------------------
__global__ void rope_kernel(const float* __restrict__ cosb,
                            const float* __restrict__ sinb, int which)
{
    float* buf = which ? g_k : g_q;
    int nh = which ? KVH_ : H_;
    int idx = blockIdx.x * blockDim.x + threadIdx.x;
    int total = B_ * S_ * nh * 32;
    if (idx >= total) return;
    int d = idx & 31;
    int h = (idx >> 5) % nh;
    int s = (idx / (32 * nh)) % S_;
    int b = idx / (32 * nh * S_);
    float* row = buf + (((size_t)(b * S_ + s)) * nh + h) * 64;
    float c1 = cosb[s * 64 + d],      s1 = sinb[s * 64 + d];
    float c2 = cosb[s * 64 + d + 32], s2 = sinb[s * 64 + d + 32];
    float x1 = row[d], x2 = row[d + 32];
    row[d]      = x1 * c1 - x2 * s1;
    row[d + 32] = x2 * c2 + x1 * s2;
}

// ---------------------------------------------------------------------------
// Flash attention, tf32 mma.sync + register prefetch of next K/V tile.
// Block = 128 q-rows x (head, batch). Warp w owns rows w*16..w*16+15.
// Epilogue writes tf32-rounded output (feeds pre-rounded A of out-gemm).
// ---------------------------------------------------------------------------
__global__ __launch_bounds__(256) void flash_mma_kernel()
{
    __shared__ __align__(16) float sK[64][68];
    __shared__ __align__(16) float sV[64][72];

    const int tid = threadIdx.x;
    const int wid = tid >> 5, lane = tid & 31;
    const int g = lane >> 2, c = lane & 3;
    const int qb = blockIdx.x, h = blockIdx.y, b = blockIdx.z;
    const int kvh = h >> 2;

    const float* qbase = g_q + ((size_t)(b * S_ + qb * 128 + wid * 16) * H_ + h) * 64;
    float qa[8][4];
    #pragma unroll
    for (int kc = 0; kc < 8; kc++) {
        qa[kc][0] = tf32r(qbase[(size_t)g * 2048       + kc * 8 + c]     * 0.125f);
        qa[kc][1] = tf32r(qbase[(size_t)(g + 8) * 2048 + kc * 8 + c]     * 0.125f);
        qa[kc][2] = tf32r(qbase[(size_t)g * 2048       + kc * 8 + c + 4] * 0.125f);
        qa[kc][3] = tf32r(qbase[(size_t)(g + 8) * 2048 + kc * 8 + c + 4] * 0.125f);
    }

    float o[8][4];
    #pragma unroll
    for (int dt = 0; dt < 8; dt++)
        #pragma unroll
        for (int e = 0; e < 4; e++) o[dt][e] = 0.f;
    float m0 = -1.0e30f, m1 = -1.0e30f, l0 = 0.f, l1 = 0.f;

    const float* kvK = g_k + ((size_t)(b * S_) * KVH_ + kvh) * 64;
    const float* kvV = g_v + ((size_t)(b * S_) * KVH_ + kvh) * 64;

    // per-thread load slots: idx = tid + u*256 -> r = idx>>4, c4 = idx&15
    float4 kr[4], vr[4];
    #pragma unroll
    for (int u = 0; u < 4; u++) {
        int idx = tid + u * 256;
        int r = idx >> 4, c4 = idx & 15;
        kr[u] = *(const float4*)(kvK + (size_t)r * 512 + c4 * 4);
        vr[u] = *(const float4*)(kvV + (size_t)r * 512 + c4 * 4);
    }

    for (int jt = 0; jt < 16; ++jt) {
        __syncthreads();   // previous tile's smem reads done
        #pragma unroll
        for (int u = 0; u < 4; u++) {
            int idx = tid + u * 256;
            int r = idx >> 4, c4 = idx & 15;
            *(float4*)&sK[r][c4 * 4] = tf32r4(kr[u]);
            *(float4*)&sV[r][c4 * 4] = tf32r4(vr[u]);
        }
        __syncthreads();

        if (jt < 15) {   // prefetch next tile while computing this one
            const float* kn = kvK + (size_t)(jt + 1) * 64 * 512;
            const float* vn = kvV + (size_t)(jt + 1) * 64 * 512;
            #pragma unroll
            for (int u = 0; u < 4; u++) {
                int idx = tid + u * 256;
                int r = idx >> 4, c4 = idx & 15;
                kr[u] = *(const float4*)(kn + (size_t)r * 512 + c4 * 4);
                vr[u] = *(const float4*)(vn + (size_t)r * 512 + c4 * 4);
            }
        }

        float s[8][4];
        #pragma unroll
        for (int nt = 0; nt < 8; nt++)
            #pragma unroll
            for (int e = 0; e < 4; e++) s[nt][e] = 0.f;
        #pragma unroll
        for (int nt = 0; nt < 8; nt++) {
            #pragma unroll
            for (int kc = 0; kc < 8; kc++) {
                float bf[2];
                bf[0] = sK[nt * 8 + g][kc * 8 + c];
                bf[1] = sK[nt * 8 + g][kc * 8 + c + 4];
                mma_tf32f(s[nt], qa[kc], bf);
            }
        }

        float tm0 = -1.0e30f, tm1 = -1.0e30f;
        #pragma unroll
        for (int nt = 0; nt < 8; nt++) {
            tm0 = fmaxf(tm0, fmaxf(s[nt][0], s[nt][1]));
            tm1 = fmaxf(tm1, fmaxf(s[nt][2], s[nt][3]));
        }
        tm0 = fmaxf(tm0, __shfl_xor_sync(0xffffffffu, tm0, 1));
        tm0 = fmaxf(tm0, __shfl_xor_sync(0xffffffffu, tm0, 2));
        tm1 = fmaxf(tm1, __shfl_xor_sync(0xffffffffu, tm1, 1));
        tm1 = fmaxf(tm1, __shfl_xor_sync(0xffffffffu, tm1, 2));

        float nm0 = fmaxf(m0, tm0), nm1 = fmaxf(m1, tm1);
        float al0 = __expf(m0 - nm0), al1 = __expf(m1 - nm1);
        m0 = nm0; m1 = nm1;

        float sum0 = 0.f, sum1 = 0.f;
        #pragma unroll
        for (int nt = 0; nt < 8; nt++) {
            s[nt][0] = tf32r(__expf(s[nt][0] - nm0));
            s[nt][1] = tf32r(__expf(s[nt][1] - nm0));
            s[nt][2] = tf32r(__expf(s[nt][2] - nm1));
            s[nt][3] = tf32r(__expf(s[nt][3] - nm1));
            sum0 += s[nt][0] + s[nt][1];
            sum1 += s[nt][2] + s[nt][3];
        }
        sum0 += __shfl_xor_sync(0xffffffffu, sum0, 1);
        sum0 += __shfl_xor_sync(0xffffffffu, sum0, 2);
        sum1 += __shfl_xor_sync(0xffffffffu, sum1, 1);
        sum1 += __shfl_xor_sync(0xffffffffu, sum1, 2);
        l0 = l0 * al0 + sum0;
        l1 = l1 * al1 + sum1;

        #pragma unroll
        for (int dt = 0; dt < 8; dt++) {
            o[dt][0] *= al0; o[dt][1] *= al0;
            o[dt][2] *= al1; o[dt][3] *= al1;
        }

        const int qbase_l = lane & ~3;
        const int src0 = qbase_l + (c >> 1);
        const int src1 = src0 + 2;
        const int e = c & 1;
        #pragma unroll
        for (int kc = 0; kc < 8; kc++) {
            float t00 = __shfl_sync(0xffffffffu, s[kc][0], src0);
            float t01 = __shfl_sync(0xffffffffu, s[kc][1], src0);
            float t02 = __shfl_sync(0xffffffffu, s[kc][2], src0);
            float t03 = __shfl_sync(0xffffffffu, s[kc][3], src0);
            float t10 = __shfl_sync(0xffffffffu, s[kc][0], src1);
            float t11 = __shfl_sync(0xffffffffu, s[kc][1], src1);
            float t12 = __shfl_sync(0xffffffffu, s[kc][2], src1);
            float t13 = __shfl_sync(0xffffffffu, s[kc][3], src1);
            float a[4];
            a[0] = e ? t01 : t00;
            a[1] = e ? t03 : t02;
            a[2] = e ? t11 : t10;
            a[3] = e ? t13 : t12;
            #pragma unroll
            for (int dt = 0; dt < 8; dt++) {
                float bf[2];
                bf[0] = sV[kc * 8 + c][dt * 8 + g];
                bf[1] = sV[kc * 8 + c + 4][dt * 8 + g];
                mma_tf32f(o[dt], a, bf);
            }
        }
    }

    float inv0 = 1.f / l0, inv1 = 1.f / l1;
    float* obase = g_attn + ((size_t)(b * S_ + qb * 128 + wid * 16) * H_ + h) * 64;
    #pragma unroll
    for (int dt = 0; dt < 8; dt++) {
        *(float2*)&obase[(size_t)g * 2048 + dt * 8 + 2 * c] =
            make_float2(tf32r(o[dt][0] * inv0), tf32r(o[dt][1] * inv0));
        *(float2*)&obase[(size_t)(g + 8) * 2048 + dt * 8 + 2 * c] =
            make_float2(tf32r(o[dt][2] * inv1), tf32r(o[dt][3] * inv1));
    }
}

// ---------------------------------------------------------------------------
extern "C" void kernel_launch(void* const* d_in, const int* in_sizes, int n_in,
                              void* d_out, int out_size)
{
    (void)in_sizes; (void)n_in; (void)out_size;
    const float* x   = (const float*)d_in[0];
    const float* cb  = (const float*)d_in[1];
    const float* sb  = (const float*)d_in[2];
    const float* Wq  = (const float*)d_in[3];
    const float* Wk  = (const float*)d_in[4];
    const float* Wv  = (const float*)d_in[5];
    const float* Wo  = (const float*)d_in[6];
    float* out = (float*)d_out;

    const int GEMM_SMEM = STAGES * (ASTG + BSTG) * 4;   // 74752 B
    cudaFuncSetAttribute(qkv_gemm_tc, cudaFuncAttributeMaxDynamicSharedMemorySize, GEMM_SMEM);
    cudaFuncSetAttribute(out_gemm_tc, cudaFuncAttributeMaxDynamicSharedMemorySize, GEMM_SMEM);

    float* xr; float* wqr; float* wkr; float* wvr; float* wor;
    cudaGetSymbolAddress((void**)&xr,  g_xr);
    cudaGetSymbolAddress((void**)&wqr, g_Wqr);
    cudaGetSymbolAddress((void**)&wkr, g_Wkr);
    cudaGetSymbolAddress((void**)&wvr, g_Wvr);
    cudaGetSymbolAddress((void**)&wor, g_Wor);

    round_kernel<<<(8388608 / 4 + 255) / 256, 256>>>(x,  xr,  8388608 / 4);
    round_kernel<<<(4194304 / 4 + 255) / 256, 256>>>(Wq, wqr, 4194304 / 4);
    round_kernel<<<(1048576 / 4 + 255) / 256, 256>>>(Wk, wkr, 1048576 / 4);
    round_kernel<<<(1048576 / 4 + 255) / 256, 256>>>(Wv, wvr, 1048576 / 4);
    round_kernel<<<(4194304 / 4 + 255) / 256, 256>>>(Wo, wor, 4194304 / 4);

    qkv_gemm_tc<<<dim3(3072 / 128, 4096 / 128), 256, GEMM_SMEM>>>(xr);

    rope_kernel<<<(B_ * S_ * H_ * 32 + 255) / 256, 256>>>(cb, sb, 0);
    rope_kernel<<<(B_ * S_ * KVH_ * 32 + 255) / 256, 256>>>(cb, sb, 1);

    flash_mma_kernel<<<dim3(S_ / 128, H_, B_), 256>>>();

    out_gemm_tc<<<dim3(2048 / 128, 4096 / 128), 256, GEMM_SMEM>>>(out);
}